// round 16
// baseline (speedup 1.0000x reference)
#include <cuda_runtime.h>
#include <cuda_bf16.h>
#include <cuda_fp16.h>
#include <cstdint>

// Problem constants
#define BSZ   32
#define SSZ   1024
#define DSZ   768
#define HSZ   128
#define RSZ   48
#define APP   (SSZ + 1)        // 1025
#define NTOK  (BSZ * SSZ)      // 32768
#define MHEAD (BSZ * APP)      // 32800

// Scratch (device globals)
__device__ __half g_headH[(size_t)MHEAD * HSZ];           // fp16 head
__device__ __half g_tailH[(size_t)NTOK * HSZ];            // fp16 tail
__device__ __half g_W16[(size_t)2 * HSZ * DSZ];           // W^T [branch][n][k] fp16
// Fragment-ordered fp16 B image per r: uint4 units: r*2048 + ks*256 + g*32 + lane
__device__ uint4 g_Bfrag[(size_t)RSZ * 2048];

// ---------------------------------------------------------------------------
// PTX helpers (target-suffix-free)
// ---------------------------------------------------------------------------
__device__ __forceinline__ uint32_t smem_u32(const void* p) {
    uint32_t a;
    asm("{ .reg .u64 t; cvta.to.shared.u64 t, %1; cvt.u32.u64 %0, t; }" : "=r"(a) : "l"(p));
    return a;
}

#define CP16(dst, src) \
    asm volatile("cp.async.cg.shared.global [%0], [%1], 16;" :: "r"(dst), "l"(src) : "memory")
#define CP_COMMIT() asm volatile("cp.async.commit_group;" ::: "memory")
#define CP_WAIT0()  asm volatile("cp.async.wait_group 0;" ::: "memory")
#define CP_WAIT1()  asm volatile("cp.async.wait_group 1;" ::: "memory")

#define LDMX4(r, addr) \
    asm volatile("ldmatrix.sync.aligned.m8n8.x4.shared.b16 {%0,%1,%2,%3}, [%4];" \
        : "=r"((r)[0]), "=r"((r)[1]), "=r"((r)[2]), "=r"((r)[3]) : "r"(addr))

// fp16 MMA
#define MMA_FP(c, a, b0, b1) \
    asm volatile("mma.sync.aligned.m16n8k16.row.col.f32.f16.f16.f32 " \
        "{%0,%1,%2,%3}, {%4,%5,%6,%7}, {%8,%9}, {%0,%1,%2,%3};" \
        : "+f"((c)[0]), "+f"((c)[1]), "+f"((c)[2]), "+f"((c)[3]) \
        : "r"((a)[0]), "r"((a)[1]), "r"((a)[2]), "r"((a)[3]), "r"(b0), "r"(b1))

__device__ __forceinline__ uint32_t pack_fp16(__half a, __half b) {
    return (uint32_t)__half_as_ushort(a) | ((uint32_t)__half_as_ushort(b) << 16);
}

// ---------------------------------------------------------------------------
// Kernel 0: fused prep. grid (48, 5).  (proven in R14)
// ---------------------------------------------------------------------------
__global__ __launch_bounds__(256) void prep_all(const float* __restrict__ Kmat,
                                                const float* __restrict__ Wh,
                                                const float* __restrict__ Wt)
{
    __shared__ float stage[32 * 129];
    const int tid = threadIdx.x;

    if (blockIdx.y < 4) {
        const int r = blockIdx.x;
        const int q = blockIdx.y;
#pragma unroll
        for (int j = 0; j < 16; j++) {
            int idx = tid + j * 256;
            int h = idx >> 7, n = idx & 127;
            stage[h * 129 + n] = Kmat[(size_t)(q * 32 + h) * (HSZ * RSZ) + r * HSZ + n];
        }
        __syncthreads();

        uint32_t* outH = (uint32_t*)(g_Bfrag + (size_t)r * 2048);
#pragma unroll
        for (int j = 0; j < 8; j++) {
            int v = q * 2048 + tid + j * 256;
            int ks   = v >> 10;
            int rem  = v & 1023;
            int g    = rem >> 7;
            int rem2 = rem & 127;
            int lane = rem2 >> 2;
            int hw2  = rem2 & 3;
            int pair = hw2 >> 1, reg = hw2 & 1;
            int n  = (2 * g + pair) * 8 + (lane >> 2);
            int h0 = ks * 16 + reg * 8 + (lane & 3) * 2 - q * 32;
            float f0 = stage[h0 * 129 + n];
            float f1 = stage[(h0 + 1) * 129 + n];
            outH[v] = pack_fp16(__float2half_rn(f0), __float2half_rn(f1));
        }
    } else {
        if (blockIdx.x >= 48) return;
        const int kb = blockIdx.x % 24;
        const int br = blockIdx.x / 24;
        const float* W = br ? Wt : Wh;
#pragma unroll
        for (int j = 0; j < 16; j++) {
            int idx = tid + j * 256;
            int k = idx >> 7;
            int n = idx & 127;
            stage[k * 129 + n] = W[(size_t)(kb * 32 + k) * HSZ + n];
        }
        __syncthreads();
#pragma unroll
        for (int j = 0; j < 16; j++) {
            int idx = tid + j * 256;
            int n = idx >> 5;
            int k = idx & 31;
            g_W16[(size_t)br * HSZ * DSZ + (size_t)n * DSZ + kb * 32 + k] =
                __float2half_rn(stage[k * 129 + n]);
        }
    }
}

// ---------------------------------------------------------------------------
// Kernel 1: FUSED dual FF GEMM. 512 threads; warps 0-7: head (Wh), 8-15: tail.
//   Per-branch warp grid 2(wm) x 4(wn), warp tile m64 x n32 (R14 geometry).
//   A tile (x rows, fp32 -> fp16) staged ONCE, shared by both branches.
//   Block 256 (grid.x = 257) computes the root head row exactly in fp32.
// ---------------------------------------------------------------------------
#define FFROW 80
#define FF_AT (128 * FFROW)                        // 10240 (A tile)
#define FF_BB FF_AT                                // B buffers: [stage][branch]
#define FF_BS (2 * FF_AT)                          // per-stage (2 branches)
#define FF_SMEM (FF_BB + 2 * FF_BS)                // 51200

__global__ __launch_bounds__(512) void ff_fused(
    const float* __restrict__ x,
    const float* __restrict__ root,
    const float* __restrict__ Wh,
    const float* __restrict__ bh, const float* __restrict__ bt)
{
    const int tid = threadIdx.x;

    // ---- root block: exact fp32 head row for the root, broadcast to all b ----
    if (blockIdx.x == 256) {
        if (tid < HSZ) {
            float s = bh[tid];
            for (int k = 0; k < DSZ; k++)
                s += root[k] * Wh[(size_t)k * HSZ + tid];
            __half hv = __float2half_rn(fmaxf(s, 0.f));
#pragma unroll 1
            for (int b = 0; b < BSZ; b++)
                g_headH[(size_t)b * APP * HSZ + tid] = hv;
        }
        return;
    }

    extern __shared__ char sm[];
    const uint32_t sb = smem_u32(sm);

    const int m0   = blockIdx.x * 128;
    const int lane = tid & 31;
    const int warp = tid >> 5;          // 0..15
    const int branch = warp >> 3;       // 0 = head, 1 = tail
    const int w8   = warp & 7;
    const int wm   = w8 >> 2;           // 0..1
    const int wn   = w8 & 3;            // 0..3

    const float* bias = (branch == 0) ? bh : bt;

    // per-thread A rows (2 float4 per chunk), dense x rows (no gather)
    int rown[2], colf[2];
    const float* arow[2];
#pragma unroll
    for (int i = 0; i < 2; i++) {
        int c   = tid + i * 512;        // 0..1023
        int row = c >> 3;
        int c4  = c & 7;
        rown[i] = row; colf[i] = c4;
        arow[i] = x + (size_t)(m0 + row) * DSZ;
    }

    // B loader: both branches, 1024 x 16B chunks, 2 per thread
    auto load_B = [&](int stage, int k0) {
#pragma unroll
        for (int i = 0; i < 2; i++) {
            int c   = tid + i * 512;    // 0..1023
            int b   = c >> 9;           // branch
            int cc  = c & 511;
            int row = cc >> 2;
            int c4  = cc & 3;
            uint32_t dst = sb + FF_BB + (uint32_t)(stage * 2 + b) * FF_AT
                         + (uint32_t)row * FFROW + c4 * 16;
            CP16(dst, g_W16 + (size_t)b * HSZ * DSZ + (size_t)row * DSZ + k0 + c4 * 8);
        }
    };

    float4 va[2];
#pragma unroll
    for (int i = 0; i < 2; i++)
        va[i] = *(const float4*)(arow[i] + colf[i] * 4);
    load_B(0, 0);
    CP_COMMIT();

    float acc[4][4][4];
#pragma unroll
    for (int mt = 0; mt < 4; mt++)
#pragma unroll
        for (int nt = 0; nt < 4; nt++)
#pragma unroll
            for (int e = 0; e < 4; e++) acc[mt][nt][e] = 0.f;

    const uint32_t aLaneOff = (uint32_t)(wm * 64 + (lane & 15)) * FFROW
                            + (uint32_t)(lane >> 4) * 16;
    const uint32_t bLaneOff = (uint32_t)(wn * 32 + (lane & 7) + ((lane >> 4) << 3)) * FFROW
                            + (uint32_t)((lane >> 3) & 1) * 16;

#pragma unroll 1
    for (int ch = 0; ch < 24; ch++) {
        const int nxt = ch + 1;
        if (nxt < 24) load_B(nxt & 1, nxt * 32);
        CP_COMMIT();

        // convert + STS A chunk ch (shared by both branches)
#pragma unroll
        for (int i = 0; i < 2; i++) {
            uint32_t w0 = pack_fp16(__float2half_rn(va[i].x), __float2half_rn(va[i].y));
            uint32_t w1 = pack_fp16(__float2half_rn(va[i].z), __float2half_rn(va[i].w));
            *(uint2*)(sm + rown[i] * FFROW + colf[i] * 8) = make_uint2(w0, w1);
        }
        if (nxt < 24) {
#pragma unroll
            for (int i = 0; i < 2; i++)
                va[i] = *(const float4*)(arow[i] + nxt * 32 + colf[i] * 4);
        }
        CP_WAIT1();
        __syncthreads();

        const uint32_t aB = sb + aLaneOff;
        const uint32_t bB = sb + FF_BB + (uint32_t)((ch & 1) * 2 + branch) * FF_AT
                          + bLaneOff;
#pragma unroll
        for (int ks = 0; ks < 2; ks++) {
            uint32_t aF[4][4];
#pragma unroll
            for (int mt = 0; mt < 4; mt++)
                LDMX4(aF[mt], aB + (uint32_t)mt * 16 * FFROW + (uint32_t)ks * 32);
            uint32_t bF[2][4];
#pragma unroll
            for (int np = 0; np < 2; np++)
                LDMX4(bF[np], bB + (uint32_t)np * 16 * FFROW + (uint32_t)ks * 32);
#pragma unroll
            for (int mt = 0; mt < 4; mt++)
#pragma unroll
                for (int nt = 0; nt < 4; nt++)
                    MMA_FP(acc[mt][nt], aF[mt],
                           bF[nt >> 1][(nt & 1) * 2], bF[nt >> 1][(nt & 1) * 2 + 1]);
        }
        __syncthreads();
    }

    float2 bv[4];
#pragma unroll
    for (int nt = 0; nt < 4; nt++)
        bv[nt] = *(const float2*)&bias[wn * 32 + nt * 8 + (lane & 3) * 2];

#pragma unroll
    for (int mt = 0; mt < 4; mt++) {
#pragma unroll
        for (int half = 0; half < 2; half++) {
            const int row = wm * 64 + mt * 16 + (lane >> 2) + half * 8;
            const int t   = m0 + row;
            // head goes to appended index (root at slot 0 per batch)
            const size_t obase = (branch == 0)
                ? ((size_t)(t >> 10) * APP + (t & 1023) + 1) * HSZ
                : (size_t)t * HSZ;
            __half* outp = (branch == 0) ? g_headH : g_tailH;
#pragma unroll
            for (int nt = 0; nt < 4; nt++) {
                const int col = wn * 32 + nt * 8 + (lane & 3) * 2;
                float f0 = fmaxf(acc[mt][nt][half * 2 + 0] + bv[nt].x, 0.f);
                float f1 = fmaxf(acc[mt][nt][half * 2 + 1] + bv[nt].y, 0.f);
                *(uint32_t*)&outp[obase + col] =
                    pack_fp16(__float2half_rn(f0), __float2half_rn(f1));
            }
        }
    }
}

// ---------------------------------------------------------------------------
// Kernel 2: biaffine v11 (R14 proven): m32 x n64, 128 tok x 6 r, 2 CTA/SM,
// deferred output via redA/redB slots + one barrier + coalesced store.
// ---------------------------------------------------------------------------
#define AROW 272
#define ATILE (128 * AROW)             // 34816
#define TTILE (128 * AROW)
#define BI_REDA (ATILE + TTILE)        // 69632
#define BI_REDB (BI_REDA + 6 * 128 * 4)    // +3072
#define BI_SMEM (BI_REDB + 6 * 128 * 4)    // 75776

__global__ __launch_bounds__(256, 2) void biaffine_mma(
    const int* __restrict__ head_id,
    float* __restrict__ out)
{
    extern __shared__ char sm[];
    const uint32_t sb = smem_u32(sm);
    float* redA = (float*)(sm + BI_REDA);
    float* redB = (float*)(sm + BI_REDB);

    const int t0  = blockIdx.x * 128;
    const int r0  = blockIdx.y * 6;
    const int tid = threadIdx.x;
    const int lane = tid & 31;
    const int warp = tid >> 5;
    const int wm   = warp >> 1;        // 0..3 (32 tokens each)
    const int wn   = warp & 1;         // 0..1 (64 k-cols each)

#pragma unroll
    for (int i = 0; i < 8; i++) {
        int c   = tid + i * 256;
        int row = c >> 4;
        int col = c & 15;
        int t   = t0 + row;
        int hid = head_id[t];
        size_t hbase = ((size_t)(t >> 10) * APP + hid) * HSZ + col * 8;
        CP16(sb + (uint32_t)row * AROW + col * 16, g_headH + hbase);
        CP16(sb + ATILE + (uint32_t)row * AROW + col * 16,
             g_tailH + (size_t)t * HSZ + col * 8);
    }
    CP_COMMIT();
    CP_WAIT0();
    __syncthreads();

    const uint32_t aBase = sb + (uint32_t)(wm * 32 + (lane & 15)) * AROW
                         + (uint32_t)(lane >> 4) * 16;

    const char* tbase = sm + ATILE
                      + ((uint32_t)(wm * 32 + (lane >> 2)) * AROW)
                      + (uint32_t)(wn * 64 + (lane & 3) * 2) * 2;

    float* rbuf = (wn == 0) ? redA : redB;

#pragma unroll 1
    for (int rr = 0; rr < 6; rr++) {
        const int r = r0 + rr;
        const uint4* __restrict__ bF = g_Bfrag + (size_t)r * 2048 + wn * 128 + lane;

        float acc[2][8][4];
#pragma unroll
        for (int mt = 0; mt < 2; mt++)
#pragma unroll
            for (int nb = 0; nb < 8; nb++)
#pragma unroll
                for (int e = 0; e < 4; e++) acc[mt][nb][e] = 0.f;

#pragma unroll
        for (int ks = 0; ks < 8; ks++) {
            uint32_t a0[4], a1[4];
            LDMX4(a0, aBase + ks * 32);
            LDMX4(a1, aBase + 16 * AROW + ks * 32);
            const uint4* bk = bF + ks * 256;
#pragma unroll
            for (int gl = 0; gl < 4; gl++) {
                uint4 bv = bk[gl * 32];
                MMA_FP(acc[0][2 * gl],     a0, bv.x, bv.y);
                MMA_FP(acc[0][2 * gl + 1], a0, bv.z, bv.w);
                MMA_FP(acc[1][2 * gl],     a1, bv.x, bv.y);
                MMA_FP(acc[1][2 * gl + 1], a1, bv.z, bv.w);
            }
        }

#pragma unroll
        for (int mt = 0; mt < 2; mt++) {
#pragma unroll
            for (int half = 0; half < 2; half++) {
                const char* trow = tbase + (uint32_t)(mt * 16 + half * 8) * AROW;
                float s = 0.f;
#pragma unroll
                for (int nb = 0; nb < 8; nb++) {
                    uint32_t tv = *(const uint32_t*)(trow + nb * 16);
                    float2 tf = __half22float2(*(const __half2*)&tv);
                    s += acc[mt][nb][half * 2 + 0] * tf.x
                       + acc[mt][nb][half * 2 + 1] * tf.y;
                }
                s += __shfl_xor_sync(0xffffffffu, s, 1);
                s += __shfl_xor_sync(0xffffffffu, s, 2);
                if ((lane & 3) == 0) {
                    int lrow = wm * 32 + mt * 16 + (lane >> 2) + half * 8;
                    rbuf[rr * 128 + lrow] = s;
                }
            }
        }
    }

    __syncthreads();
#pragma unroll
    for (int i = 0; i < 3; i++) {
        int idx  = tid + i * 256;          // 0..767
        int lrow = idx / 6;
        int rr   = idx - lrow * 6;
        out[(size_t)(t0 + lrow) * RSZ + (r0 + rr)] =
            redA[rr * 128 + lrow] + redB[rr * 128 + lrow];
    }
}

// ---------------------------------------------------------------------------
extern "C" void kernel_launch(void* const* d_in, const int* in_sizes, int n_in,
                              void* d_out, int out_size)
{
    const float* x       = (const float*)d_in[0];
    const int*   head_id = (const int*)  d_in[1];
    const float* root    = (const float*)d_in[2];
    const float* Wh      = (const float*)d_in[3];
    const float* bh      = (const float*)d_in[4];
    const float* Wt      = (const float*)d_in[5];
    const float* bt      = (const float*)d_in[6];
    const float* Kmat    = (const float*)d_in[7];
    float*       out     = (float*)d_out;

    prep_all<<<dim3(RSZ, 5), 256>>>(Kmat, Wh, Wt);

    cudaFuncSetAttribute(ff_fused, cudaFuncAttributeMaxDynamicSharedMemorySize, FF_SMEM);
    ff_fused<<<257, 512, FF_SMEM>>>(x, root, Wh, bh, bt);

    cudaFuncSetAttribute(biaffine_mma, cudaFuncAttributeMaxDynamicSharedMemorySize, BI_SMEM);
    biaffine_mma<<<dim3(NTOK / 128, RSZ / 6), 256, BI_SMEM>>>(head_id, out);
}